// round 3
// baseline (speedup 1.0000x reference)
#include <cuda_runtime.h>
#include <math.h>
#include <stdint.h>

#define CIN 48
#define CB  8
#define H   4096
#define HV  (H/4)                 // 1024 float4 per channel row
#define NCHUNK 4                  // h-chunks per batch
#define CHUNK_F4 (HV / NCHUNK)    // 256 float4 per chunk
#define NT 256                    // threads per CTA
#define NW (NT/32)                // 8 warps
#define NPAIR 36
#define SCALE 0.35355339059327373f

// persistent scratch (allowed: __device__ globals, no runtime alloc)
__device__ float g_kqv[256 * CB * H];          // 32 MB, [b][o][h]
__device__ float g_gpart[256 * NCHUNK * NPAIR];

// ---------------------------------------------------------------------------
// K1: kqv = w_down @ x  (write to scratch) + exact fp32 gram partials
// grid = 256*NCHUNK CTAs of 256 threads; thread = one float4 of h
// ---------------------------------------------------------------------------
__global__ __launch_bounds__(NT)
void k1_down_gram(const float* __restrict__ x,
                  const float* __restrict__ wd)
{
    __shared__ float s_wd[CB * CIN];           // 384
    __shared__ float s_gpart[NW * NPAIR];      // 8*36

    const int b     = blockIdx.x >> 2;
    const int chunk = blockIdx.x & 3;
    const int t     = threadIdx.x;
    const int lane  = t & 31;
    const int warp  = t >> 5;

    if (t < CB * CIN)      s_wd[t]       = wd[t];
    else if (t - NT + NT < CB * CIN + NT && (t + NT) < CB * CIN + NT) {}
    if (t + NT < CB * CIN) s_wd[t + NT]  = wd[t + NT];
    __syncthreads();

    const float4* __restrict__ x4 = (const float4*)(x + (size_t)b * CIN * H);
    const int p = chunk * CHUNK_F4 + t;        // float4 index within row

    float acc[CB][4];
    #pragma unroll
    for (int o = 0; o < CB; o++) {
        acc[o][0] = 0.f; acc[o][1] = 0.f; acc[o][2] = 0.f; acc[o][3] = 0.f;
    }

    #pragma unroll 4
    for (int c = 0; c < CIN; c++) {
        float4 xv = __ldcs(&x4[c * HV + p]);
        #pragma unroll
        for (int o = 0; o < CB; o++) {
            float w = s_wd[o * CIN + c];
            acc[o][0] += w * xv.x;
            acc[o][1] += w * xv.y;
            acc[o][2] += w * xv.z;
            acc[o][3] += w * xv.w;
        }
    }

    // write kqv to scratch (default caching -> lands in L2 for K2)
    float4* __restrict__ kqv4 = (float4*)(g_kqv + (size_t)b * CB * H);
    #pragma unroll
    for (int o = 0; o < CB; o++) {
        float4 v;
        v.x = acc[o][0]; v.y = acc[o][1]; v.z = acc[o][2]; v.w = acc[o][3];
        kqv4[o * HV + p] = v;
    }

    // gram partials (exact fp32): 36 upper-tri pairs, warp-reduced
    {
        int base = 0;
        #pragma unroll
        for (int i = 0; i < CB; i++) {
            #pragma unroll
            for (int j = i; j < CB; j++) {
                float s = acc[i][0] * acc[j][0] + acc[i][1] * acc[j][1]
                        + acc[i][2] * acc[j][2] + acc[i][3] * acc[j][3];
                #pragma unroll
                for (int off = 16; off > 0; off >>= 1)
                    s += __shfl_xor_sync(0xffffffffu, s, off);
                if (lane == 0) s_gpart[warp * NPAIR + base] = s;
                base++;
            }
        }
    }
    __syncthreads();

    if (t < NPAIR) {
        float s = 0.f;
        #pragma unroll
        for (int w = 0; w < NW; w++) s += s_gpart[w * NPAIR + t];
        g_gpart[(b * NCHUNK + chunk) * NPAIR + t] = s;
    }
}

// ---------------------------------------------------------------------------
// K2: gram-sum -> softmax -> W2 = w_up @ AM (tiny prologue),
//     then out = W2 @ kqv (streaming)
// grid = 256*NCHUNK CTAs of 256 threads; thread = one float4 of h
// ---------------------------------------------------------------------------
__global__ __launch_bounds__(NT)
void k2_softmax_up(const float* __restrict__ wu,
                   float* __restrict__ out)
{
    __shared__ float s_G[CB * CB];
    __shared__ float s_AM[CB * CB];
    __shared__ float s_W2[CIN * CB];

    const int b     = blockIdx.x >> 2;
    const int chunk = blockIdx.x & 3;
    const int t     = threadIdx.x;
    const int p     = chunk * CHUNK_F4 + t;

    // start kqv loads early (independent of prologue)
    const float4* __restrict__ kqv4 = (const float4*)(g_kqv + (size_t)b * CB * H);
    float k[CB][4];
    #pragma unroll
    for (int o = 0; o < CB; o++) {
        float4 v = kqv4[o * HV + p];
        k[o][0] = v.x; k[o][1] = v.y; k[o][2] = v.z; k[o][3] = v.w;
    }

    // ---- prologue: G -> AM -> W2 (redundant per chunk, trivial cost) ----
    if (t < NPAIR) {
        float s = 0.f;
        #pragma unroll
        for (int c = 0; c < NCHUNK; c++)
            s += g_gpart[(b * NCHUNK + c) * NPAIR + t];
        int i = 0, rem = t;
        while (rem >= CB - i) { rem -= CB - i; i++; }
        int j = i + rem;
        s_G[i * CB + j] = s;
        s_G[j * CB + i] = s;
    }
    __syncthreads();

    if (t < CB) {
        float v[CB];
        float m = -1e30f;
        #pragma unroll
        for (int j = 0; j < CB; j++) {
            v[j] = s_G[t * CB + j] * SCALE;
            m = fmaxf(m, v[j]);
        }
        float sum = 0.f;
        #pragma unroll
        for (int j = 0; j < CB; j++) {
            v[j] = __expf(v[j] - m);
            sum += v[j];
        }
        float inv = 1.f / sum;
        #pragma unroll
        for (int j = 0; j < CB; j++) s_AM[t * CB + j] = v[j] * inv;
    }
    __syncthreads();

    #pragma unroll
    for (int base = 0; base < CIN * CB; base += NT) {
        int idx = base + t;
        if (idx < CIN * CB) {
            int c = idx >> 3, j = idx & 7;
            float s = 0.f;
            #pragma unroll
            for (int o = 0; o < CB; o++) s += wu[c * CB + o] * s_AM[o * CB + j];
            s_W2[idx] = s;
        }
    }
    __syncthreads();

    // ---- streaming epilogue: out[c][h] = sum_j W2[c][j] * kqv[j][h] ----
    float4* __restrict__ out4 = (float4*)(out + (size_t)b * CIN * H);

    #pragma unroll 4
    for (int c = 0; c < CIN; c++) {
        const float4 w0 = ((const float4*)(s_W2 + c * CB))[0];
        const float4 w1 = ((const float4*)(s_W2 + c * CB))[1];
        float4 r;
        r.x = w0.x * k[0][0] + w0.y * k[1][0] + w0.z * k[2][0] + w0.w * k[3][0]
            + w1.x * k[4][0] + w1.y * k[5][0] + w1.z * k[6][0] + w1.w * k[7][0];
        r.y = w0.x * k[0][1] + w0.y * k[1][1] + w0.z * k[2][1] + w0.w * k[3][1]
            + w1.x * k[4][1] + w1.y * k[5][1] + w1.z * k[6][1] + w1.w * k[7][1];
        r.z = w0.x * k[0][2] + w0.y * k[1][2] + w0.z * k[2][2] + w0.w * k[3][2]
            + w1.x * k[4][2] + w1.y * k[5][2] + w1.z * k[6][2] + w1.w * k[7][2];
        r.w = w0.x * k[0][3] + w0.y * k[1][3] + w0.z * k[2][3] + w0.w * k[3][3]
            + w1.x * k[4][3] + w1.y * k[5][3] + w1.z * k[6][3] + w1.w * k[7][3];
        __stwt(&out4[c * HV + p], r);
    }
}

extern "C" void kernel_launch(void* const* d_in, const int* in_sizes, int n_in,
                              void* d_out, int out_size)
{
    const float* x  = (const float*)d_in[0];   // [256, 48, 4096, 1]
    const float* wd = (const float*)d_in[1];   // [8, 48]
    const float* wu = (const float*)d_in[2];   // [48, 8]
    float* out = (float*)d_out;                // [256, 48, 4096, 1]

    k1_down_gram<<<256 * NCHUNK, NT>>>(x, wd);
    k2_softmax_up<<<256 * NCHUNK, NT>>>(wu, out);
}

// round 4
// speedup vs baseline: 1.2531x; 1.2531x over previous
#include <cuda_runtime.h>
#include <math.h>
#include <stdint.h>

#define CIN 48
#define CB  8
#define H   4096
#define HV  (H/4)          // 1024 float4 per channel row
#define NTHREADS 1024
#define NWARPS   (NTHREADS/32)
#define NPAIR    36        // upper-triangle incl. diag of 8x8
#define SCALE    0.35355339059327373f   // 1/sqrt(8)

typedef unsigned long long ull;

// packed fp32x2 FMA / MUL (SASS FFMA2 / FMUL2 — PTX-only on sm_103a)
__device__ __forceinline__ ull fma2(ull a, ull b, ull c) {
    ull d;
    asm("fma.rn.f32x2 %0, %1, %2, %3;" : "=l"(d) : "l"(a), "l"(b), "l"(c));
    return d;
}
__device__ __forceinline__ ull mul2(ull a, ull b) {
    ull d;
    asm("mul.rn.f32x2 %0, %1, %2;" : "=l"(d) : "l"(a), "l"(b));
    return d;
}
__device__ __forceinline__ void unpack2(ull v, float& lo, float& hi) {
    asm("mov.b64 {%0, %1}, %2;" : "=f"(lo), "=f"(hi) : "l"(v));
}
__device__ __forceinline__ ull dup_f32(float f) {
    uint32_t u = __float_as_uint(f);
    return ((ull)u << 32) | (ull)u;
}

__global__ __launch_bounds__(NTHREADS, 1)
void ultimus_kernel(const float* __restrict__ x,
                    const float* __restrict__ wd,   // [8,48]
                    const float* __restrict__ wu,   // [48,8]
                    float* __restrict__ out)
{
    __shared__ ull   s_wdd[CB * CIN];          // duplicated {w,w} pairs, 3 KB
    __shared__ float s_gpart[NWARPS * NPAIR];  // 32*36
    __shared__ float s_G[CB * CB];
    __shared__ float s_AM[CB * CB];
    __shared__ ull   s_W2d[CIN * CB];          // duplicated {v,v} W2, 3 KB

    const int b    = blockIdx.x;
    const int t    = threadIdx.x;
    const int lane = t & 31;
    const int warp = t >> 5;

    if (t < CB * CIN) s_wdd[t] = dup_f32(wd[t]);
    __syncthreads();

    // ---------------- Pass 1: kqv = w_down @ x (f32x2 accumulators) --------
    const double2* __restrict__ x2 = (const double2*)(x + (size_t)b * CIN * H);

    // acc2[o][s]: s=0 -> h-slots {0,1}, s=1 -> h-slots {2,3}
    ull acc2[CB][2];
    #pragma unroll
    for (int o = 0; o < CB; o++) { acc2[o][0] = 0ull; acc2[o][1] = 0ull; }

    #pragma unroll 4
    for (int c = 0; c < CIN; c++) {
        double2 xv = __ldcs(&x2[c * HV + t]);
        ull xlo = __double_as_longlong(xv.x);
        ull xhi = __double_as_longlong(xv.y);
        #pragma unroll
        for (int o = 0; o < CB; o++) {
            ull w = s_wdd[o * CIN + c];        // LDS.64 broadcast
            acc2[o][0] = fma2(w, xlo, acc2[o][0]);
            acc2[o][1] = fma2(w, xhi, acc2[o][1]);
        }
    }

    // ---------------- Gram: G[i][j] = sum_h kqv_i * kqv_j ------------------
    {
        int base = 0;
        #pragma unroll
        for (int i = 0; i < CB; i++) {
            #pragma unroll
            for (int j = i; j < CB; j++) {
                ull p = mul2(acc2[i][0], acc2[j][0]);
                p = fma2(acc2[i][1], acc2[j][1], p);
                float plo, phi;
                unpack2(p, plo, phi);
                float s = plo + phi;
                #pragma unroll
                for (int off = 16; off > 0; off >>= 1)
                    s += __shfl_xor_sync(0xffffffffu, s, off);
                if (lane == 0) s_gpart[warp * NPAIR + base] = s;
                base++;
            }
        }
    }
    __syncthreads();

    // reduce 32 warp partials -> full symmetric G
    if (t < NPAIR) {
        float s = 0.f;
        #pragma unroll
        for (int w = 0; w < NWARPS; w++) s += s_gpart[w * NPAIR + t];
        int i = 0, rem = t;
        while (rem >= CB - i) { rem -= CB - i; i++; }
        int j = i + rem;
        s_G[i * CB + j] = s;
        s_G[j * CB + i] = s;
    }
    __syncthreads();

    // ---------------- Softmax rows of G*SCALE -> AM -------------------------
    if (t < CB) {
        float v[CB];
        float m = -1e30f;
        #pragma unroll
        for (int j = 0; j < CB; j++) {
            v[j] = s_G[t * CB + j] * SCALE;
            m = fmaxf(m, v[j]);
        }
        float sum = 0.f;
        #pragma unroll
        for (int j = 0; j < CB; j++) {
            v[j] = __expf(v[j] - m);
            sum += v[j];
        }
        float inv = 1.f / sum;
        #pragma unroll
        for (int j = 0; j < CB; j++) s_AM[t * CB + j] = v[j] * inv;
    }
    __syncthreads();

    // ---------------- W2[c][j] = sum_o wu[c][o] * AM[o][j], duplicated ------
    if (t < CIN * CB) {
        int c = t >> 3, j = t & 7;
        float s = 0.f;
        #pragma unroll
        for (int o = 0; o < CB; o++) s += wu[c * CB + o] * s_AM[o * CB + j];
        s_W2d[c * CB + j] = dup_f32(s);
    }
    __syncthreads();

    // ---------------- Pass 2: out[c][h] = sum_j W2[c][j] * kqv[j][h] --------
    double2* __restrict__ out2 = (double2*)(out + (size_t)b * CIN * H);

    #pragma unroll 4
    for (int c = 0; c < CIN; c++) {
        ull w0 = s_W2d[c * CB + 0];
        ull r0 = mul2(w0, acc2[0][0]);
        ull r1 = mul2(w0, acc2[0][1]);
        #pragma unroll
        for (int o = 1; o < CB; o++) {
            ull w = s_W2d[c * CB + o];         // LDS.64 broadcast
            r0 = fma2(w, acc2[o][0], r0);
            r1 = fma2(w, acc2[o][1], r1);
        }
        double2 rv;
        rv.x = __longlong_as_double((long long)r0);
        rv.y = __longlong_as_double((long long)r1);
        __stwt(&out2[c * HV + t], rv);
    }
}

extern "C" void kernel_launch(void* const* d_in, const int* in_sizes, int n_in,
                              void* d_out, int out_size)
{
    const float* x  = (const float*)d_in[0];   // [256, 48, 4096, 1]
    const float* wd = (const float*)d_in[1];   // [8, 48]
    const float* wu = (const float*)d_in[2];   // [48, 8]
    float* out = (float*)d_out;                // [256, 48, 4096, 1]

    ultimus_kernel<<<256, NTHREADS>>>(x, wd, wu, out);
}